// round 2
// baseline (speedup 1.0000x reference)
#include <cuda_runtime.h>
#include <math.h>

// Problem constants (dims are fixed by the problem; N/E read at runtime)
#define NMAX 50048
#define EMAX 600064

// ---------------- scratch (static __device__ — no allocation) ----------------
__device__ float g_qp [NMAX * 128];
__device__ float g_rkw[NMAX * 128];
__device__ float g_rvw[NMAX * 128];
__device__ float g_rkc[NMAX * 128];
__device__ float g_rvc[NMAX * 128];
__device__ float g_outp[NMAX * 128];
__device__ float g_cw[4][128 * 128];     // composed wk@wrk / wv@wrv per relation
__device__ int   g_deg[2][NMAX];
__device__ int   g_cur[2][NMAX];
__device__ int   g_off[2][NMAX + 1];
__device__ int   g_csr[2][EMAX];

__device__ __forceinline__ float* pick_dst(int which) {
    switch (which) {
        case 0: return g_qp;
        case 1: return g_rkw;
        case 2: return g_rvw;
        case 3: return g_rkc;
        default: return g_rvc;
    }
}

// ---------------- init: zero out_p / deg / cur --------------------------------
__global__ void init_zero(int n) {
    int stride = gridDim.x * blockDim.x;
    int i = blockIdx.x * blockDim.x + threadIdx.x;
    int total = n * 128;
    for (int j = i; j < total; j += stride) g_outp[j] = 0.f;
    for (int j = i; j < n; j += stride) {
        g_deg[0][j] = 0; g_deg[1][j] = 0;
        g_cur[0][j] = 0; g_cur[1][j] = 0;
    }
}

// ---------------- compose weights: C = A @ B (128x128x128) -------------------
// grid (128, 4), 128 threads. blockIdx.y selects which of the 4 matrices.
__global__ void compose_kernel(const float* __restrict__ A0, const float* __restrict__ B0,
                               const float* __restrict__ A1, const float* __restrict__ B1,
                               const float* __restrict__ A2, const float* __restrict__ B2,
                               const float* __restrict__ A3, const float* __restrict__ B3) {
    const float* A; const float* B;
    switch (blockIdx.y) {
        case 0: A = A0; B = B0; break;
        case 1: A = A1; B = B1; break;
        case 2: A = A2; B = B2; break;
        default: A = A3; B = B3; break;
    }
    float* C = g_cw[blockIdx.y];
    int i = blockIdx.x;      // output row
    int j = threadIdx.x;     // output col
    __shared__ float As[128];
    As[j] = A[i * 128 + j];
    __syncthreads();
    float acc = 0.f;
#pragma unroll 8
    for (int k = 0; k < 128; k++) acc += As[k] * B[k * 128 + j];
    C[i * 128 + j] = acc;
}

// ---------------- SGEMM: Y[nrows,128] = X[nrows,128] @ W[128,128] -------------
// BM=128, BN=128, BK=8, 256 threads, 8x8 microtile per thread.
__global__ __launch_bounds__(256) void sgemm_nn128(
    const float* __restrict__ X, const float* __restrict__ Wext,
    int wsel, int dsel, int nrows) {
    const float* W = (wsel >= 0) ? g_cw[wsel] : Wext;
    float* Y = pick_dst(dsel);

    __shared__ float As[8][128];
    __shared__ float Bs[8][128];

    int tid = threadIdx.x;
    int row0 = blockIdx.x * 128;
    int tx = tid & 15;        // 0..15  (N direction)
    int ty = tid >> 4;        // 0..15  (M direction)

    int lrow = tid >> 1;          // 0..127
    int lk4  = (tid & 1) * 4;     // 0 or 4
    int bk = tid >> 5;            // 0..7
    int bn = (tid & 31) * 4;      // 0..124

    float acc[8][8];
#pragma unroll
    for (int i = 0; i < 8; i++)
#pragma unroll
        for (int j = 0; j < 8; j++) acc[i][j] = 0.f;

    for (int k0 = 0; k0 < 128; k0 += 8) {
        float4 xa = make_float4(0.f, 0.f, 0.f, 0.f);
        int gr = row0 + lrow;
        if (gr < nrows)
            xa = *(const float4*)(X + (size_t)gr * 128 + k0 + lk4);
        As[lk4 + 0][lrow] = xa.x;
        As[lk4 + 1][lrow] = xa.y;
        As[lk4 + 2][lrow] = xa.z;
        As[lk4 + 3][lrow] = xa.w;

        float4 wb = *(const float4*)(W + (size_t)(k0 + bk) * 128 + bn);
        *(float4*)&Bs[bk][bn] = wb;
        __syncthreads();

#pragma unroll
        for (int kk = 0; kk < 8; kk++) {
            float a[8], b[8];
            float4 a0 = *(const float4*)&As[kk][ty * 8];
            float4 a1 = *(const float4*)&As[kk][ty * 8 + 4];
            a[0]=a0.x; a[1]=a0.y; a[2]=a0.z; a[3]=a0.w;
            a[4]=a1.x; a[5]=a1.y; a[6]=a1.z; a[7]=a1.w;
            float4 b0 = *(const float4*)&Bs[kk][tx * 8];
            float4 b1 = *(const float4*)&Bs[kk][tx * 8 + 4];
            b[0]=b0.x; b[1]=b0.y; b[2]=b0.z; b[3]=b0.w;
            b[4]=b1.x; b[5]=b1.y; b[6]=b1.z; b[7]=b1.w;
#pragma unroll
            for (int i = 0; i < 8; i++)
#pragma unroll
                for (int j = 0; j < 8; j++)
                    acc[i][j] += a[i] * b[j];
        }
        __syncthreads();
    }

#pragma unroll
    for (int i = 0; i < 8; i++) {
        int gr = row0 + ty * 8 + i;
        if (gr < nrows) {
            float4 v0 = make_float4(acc[i][0], acc[i][1], acc[i][2], acc[i][3]);
            float4 v1 = make_float4(acc[i][4], acc[i][5], acc[i][6], acc[i][7]);
            *(float4*)(Y + (size_t)gr * 128 + tx * 8)     = v0;
            *(float4*)(Y + (size_t)gr * 128 + tx * 8 + 4) = v1;
        }
    }
}

// ---------------- CSR build ----------------------------------------------------
__global__ void hist_kernel(const int* __restrict__ edges, int E, int rel) {
    int i = blockIdx.x * blockDim.x + threadIdx.x;
    if (i < E) atomicAdd(&g_deg[rel][edges[E + i]], 1);   // col = dst
}

// one block per relation; 1024-thread chunked Hillis-Steele exclusive scan
__global__ void scan_kernel(int n) {
    int rel = blockIdx.x;
    __shared__ int sm[1024];
    __shared__ int carry;
    int tid = threadIdx.x;
    if (tid == 0) carry = 0;
    __syncthreads();
    for (int base = 0; base < n; base += 1024) {
        int i = base + tid;
        int v = (i < n) ? g_deg[rel][i] : 0;
        sm[tid] = v;
        __syncthreads();
#pragma unroll
        for (int ofs = 1; ofs < 1024; ofs <<= 1) {
            int t = (tid >= ofs) ? sm[tid - ofs] : 0;
            __syncthreads();
            sm[tid] += t;
            __syncthreads();
        }
        if (i < n) g_off[rel][i] = carry + sm[tid] - v;   // exclusive
        int tot = sm[1023];
        __syncthreads();
        if (tid == 0) carry += tot;
        __syncthreads();
    }
    if (tid == 0) g_off[rel][n] = carry;
}

__global__ void scatter_kernel(const int* __restrict__ edges, int E, int rel) {
    int i = blockIdx.x * blockDim.x + threadIdx.x;
    if (i < E) {
        int src = edges[i];
        int dst = edges[E + i];
        int p = atomicAdd(&g_cur[rel][dst], 1);
        g_csr[rel][g_off[rel][dst] + p] = src;
    }
}

// ---------------- per-destination online-softmax aggregation ------------------
// one warp per destination node; lane l holds elements [l*4, l*4+4) of the
// 128-wide (H=4 x D=32) feature row; heads live in 8-lane groups.
__global__ __launch_bounds__(128) void aggregate_kernel(int rel, int ndst) {
    const float* rk = rel ? g_rkc : g_rkw;
    const float* rv = rel ? g_rvc : g_rvw;
    int warp = (blockIdx.x * blockDim.x + threadIdx.x) >> 5;
    if (warp >= ndst) return;
    int lane = threadIdx.x & 31;

    int beg = g_off[rel][warp];
    int end = g_off[rel][warp + 1];
    if (beg == end) return;

    float4 q4 = *(const float4*)(g_qp + (size_t)warp * 128 + lane * 4);
    float m = -INFINITY, s = 0.f;
    float4 acc = make_float4(0.f, 0.f, 0.f, 0.f);

    for (int e = beg; e < end; e++) {
        int src = g_csr[rel][e];
        const float4 rk4 = *(const float4*)(rk + (size_t)src * 128 + lane * 4);
        float p = q4.x * rk4.x + q4.y * rk4.y + q4.z * rk4.z + q4.w * rk4.w;
        // reduce over the 8 lanes of this head
        p += __shfl_xor_sync(0xFFFFFFFFu, p, 1);
        p += __shfl_xor_sync(0xFFFFFFFFu, p, 2);
        p += __shfl_xor_sync(0xFFFFFFFFu, p, 4);
        float score = p * 0.17677669529663687f;   // 1/sqrt(32)

        const float4 rv4 = *(const float4*)(rv + (size_t)src * 128 + lane * 4);
        float nm = fmaxf(m, score);
        float corr = __expf(m - nm);              // exp(-inf) == 0 on first edge
        float pe = __expf(score - nm);
        s = s * corr + pe;
        acc.x = acc.x * corr + pe * rv4.x;
        acc.y = acc.y * corr + pe * rv4.y;
        acc.z = acc.z * corr + pe * rv4.z;
        acc.w = acc.w * corr + pe * rv4.w;
        m = nm;
    }

    float inv = 1.f / s;
    float* o = g_outp + (size_t)warp * 128 + lane * 4;
    o[0] += acc.x * inv;
    o[1] += acc.y * inv;
    o[2] += acc.z * inv;
    o[3] += acc.w * inv;
}

// ---------------- final projections -------------------------------------------
// fin_a = x_author @ wr_a + bo_a            (out_a is identically zero)
__global__ __launch_bounds__(256) void final_a_kernel(
    const float* __restrict__ X, const float* __restrict__ Wr,
    const float* __restrict__ bo, float* __restrict__ out, int n) {
    __shared__ float Ws[128 * 32];
    for (int i = threadIdx.x; i < 4096; i += blockDim.x) Ws[i] = Wr[i];
    __syncthreads();
    int warp = blockIdx.x * (blockDim.x >> 5) + (threadIdx.x >> 5);
    int lane = threadIdx.x & 31;
    if (warp >= n) return;
    const float* xr = X + (size_t)warp * 128;
    float acc = bo[lane];
#pragma unroll 8
    for (int k = 0; k < 128; k++) acc += xr[k] * Ws[k * 32 + lane];
    out[(size_t)warp * 32 + lane] = acc;
}

// fin_p = out_p @ wo_p + x_paper @ wr_p + bo_p
__global__ __launch_bounds__(256) void final_p_kernel(
    const float* __restrict__ Xp, const float* __restrict__ Wo,
    const float* __restrict__ Wr, const float* __restrict__ bo,
    float* __restrict__ out, int n) {
    __shared__ float Ws[2 * 128 * 32];
    for (int i = threadIdx.x; i < 4096; i += blockDim.x) Ws[i] = Wo[i];
    for (int i = threadIdx.x; i < 4096; i += blockDim.x) Ws[4096 + i] = Wr[i];
    __syncthreads();
    int warp = blockIdx.x * (blockDim.x >> 5) + (threadIdx.x >> 5);
    int lane = threadIdx.x & 31;
    if (warp >= n) return;
    const float* op = g_outp + (size_t)warp * 128;
    const float* xr = Xp + (size_t)warp * 128;
    float acc = bo[lane];
#pragma unroll 8
    for (int k = 0; k < 128; k++) acc += op[k] * Ws[k * 32 + lane];
#pragma unroll 8
    for (int k = 0; k < 128; k++) acc += xr[k] * Ws[4096 + k * 32 + lane];
    out[(size_t)warp * 32 + lane] = acc;
}

// ---------------- launch --------------------------------------------------------
extern "C" void kernel_launch(void* const* d_in, const int* in_sizes, int n_in,
                              void* d_out, int out_size) {
    const float* x_a   = (const float*)d_in[0];
    const float* x_p   = (const float*)d_in[1];
    const int*   e_w   = (const int*)d_in[2];
    const int*   e_c   = (const int*)d_in[3];
    const float* wk_a  = (const float*)d_in[5];
    const float* wv_a  = (const float*)d_in[6];
    const float* wq_p  = (const float*)d_in[7];
    const float* wk_p  = (const float*)d_in[8];
    const float* wv_p  = (const float*)d_in[9];
    const float* wrk_w = (const float*)d_in[10];
    const float* wrv_w = (const float*)d_in[11];
    const float* wrk_c = (const float*)d_in[12];
    const float* wrv_c = (const float*)d_in[13];
    const float* bo_a  = (const float*)d_in[15];
    const float* wo_p  = (const float*)d_in[16];
    const float* bo_p  = (const float*)d_in[17];
    const float* wr_a  = (const float*)d_in[18];
    const float* wr_p  = (const float*)d_in[19];
    float* out = (float*)d_out;

    int n  = in_sizes[0] / 128;
    int Ew = in_sizes[2] / 2;
    int Ec = in_sizes[3] / 2;

    init_zero<<<512, 256>>>(n);
    compose_kernel<<<dim3(128, 4), 128>>>(wk_a, wrk_w, wv_a, wrv_w,
                                          wk_p, wrk_c, wv_p, wrv_c);

    int gb = (n + 127) / 128;
    sgemm_nn128<<<gb, 256>>>(x_p, wq_p, -1, 0, n);   // q_p
    sgemm_nn128<<<gb, 256>>>(x_a, nullptr, 0, 1, n); // rk (writes)
    sgemm_nn128<<<gb, 256>>>(x_a, nullptr, 1, 2, n); // rv (writes)
    sgemm_nn128<<<gb, 256>>>(x_p, nullptr, 2, 3, n); // rk (cites)
    sgemm_nn128<<<gb, 256>>>(x_p, nullptr, 3, 4, n); // rv (cites)

    int ge_w = (Ew + 255) / 256;
    int ge_c = (Ec + 255) / 256;
    hist_kernel<<<ge_w, 256>>>(e_w, Ew, 0);
    hist_kernel<<<ge_c, 256>>>(e_c, Ec, 1);
    scan_kernel<<<2, 1024>>>(n);
    scatter_kernel<<<ge_w, 256>>>(e_w, Ew, 0);
    scatter_kernel<<<ge_c, 256>>>(e_c, Ec, 1);

    int ga = (n + 3) / 4;   // 4 warps / 128-thread block
    aggregate_kernel<<<ga, 128>>>(0, n);
    aggregate_kernel<<<ga, 128>>>(1, n);

    int gf = (n + 7) / 8;   // 8 warps / 256-thread block
    final_a_kernel<<<gf, 256>>>(x_a, wr_a, bo_a, out, n);
    final_p_kernel<<<gf, 256>>>(x_p, wo_p, wr_p, bo_p, out + (size_t)n * 32, n);
}

// round 3
// speedup vs baseline: 1.0730x; 1.0730x over previous
#include <cuda_runtime.h>
#include <math.h>

#define NMAX 50048
#define EMAX 600064

// ---------------- scratch (static __device__ — no allocation) ----------------
__device__ float g_qp [NMAX * 128];
__device__ float g_rkw[NMAX * 128];
__device__ float g_rvw[NMAX * 128];
__device__ float g_rkc[NMAX * 128];
__device__ float g_rvc[NMAX * 128];
__device__ float g_outp[NMAX * 128];
__device__ float g_cw[4][128 * 128];
__device__ int   g_deg[2][NMAX];
__device__ int   g_cur[2][NMAX];
__device__ int   g_off[2][NMAX + 1];
__device__ int   g_csr[2][EMAX];

// ---------------- init: zero deg / cur ----------------------------------------
__global__ void init_zero(int n) {
    int i = blockIdx.x * blockDim.x + threadIdx.x;
    if (i < n) {
        g_deg[0][i] = 0; g_deg[1][i] = 0;
        g_cur[0][i] = 0; g_cur[1][i] = 0;
    }
}

// ---------------- compose weights: C = A @ B (128x128x128) --------------------
__global__ void compose_kernel(const float* __restrict__ A0, const float* __restrict__ B0,
                               const float* __restrict__ A1, const float* __restrict__ B1,
                               const float* __restrict__ A2, const float* __restrict__ B2,
                               const float* __restrict__ A3, const float* __restrict__ B3) {
    const float* A; const float* B;
    switch (blockIdx.y) {
        case 0: A = A0; B = B0; break;
        case 1: A = A1; B = B1; break;
        case 2: A = A2; B = B2; break;
        default: A = A3; B = B3; break;
    }
    float* C = g_cw[blockIdx.y];
    int i = blockIdx.x;
    int j = threadIdx.x;
    __shared__ float As[128];
    As[j] = A[i * 128 + j];
    __syncthreads();
    float acc = 0.f;
#pragma unroll 8
    for (int k = 0; k < 128; k++) acc += As[k] * B[k * 128 + j];
    C[i * 128 + j] = acc;
}

// ---------------- fused SGEMM: 5 products in one launch ------------------------
// grid (rowTiles, 5), 256 threads, BM=128 BN=128 BK=8, double-buffered smem,
// 8x8 microtile per thread.
__global__ __launch_bounds__(256, 2) void sgemm_fused(
    const float* __restrict__ x_a, const float* __restrict__ x_p,
    const float* __restrict__ wq_p, int nrows) {

    const float* X; const float* W; float* Y;
    switch (blockIdx.y) {
        case 0: X = x_p; W = wq_p;    Y = g_qp;  break;
        case 1: X = x_a; W = g_cw[0]; Y = g_rkw; break;
        case 2: X = x_a; W = g_cw[1]; Y = g_rvw; break;
        case 3: X = x_p; W = g_cw[2]; Y = g_rkc; break;
        default:X = x_p; W = g_cw[3]; Y = g_rvc; break;
    }

    __shared__ float As[2][8][128];
    __shared__ float Bs[2][8][128];

    int tid = threadIdx.x;
    int row0 = blockIdx.x * 128;
    int tx = tid & 15;
    int ty = tid >> 4;

    int lrow = tid >> 1;
    int lk4  = (tid & 1) * 4;
    int bk = tid >> 5;
    int bn = (tid & 31) * 4;

    int gr = row0 + lrow;
    bool rok = (gr < nrows);
    const float* Xp = X + (size_t)gr * 128 + lk4;

    float acc[8][8];
#pragma unroll
    for (int i = 0; i < 8; i++)
#pragma unroll
        for (int j = 0; j < 8; j++) acc[i][j] = 0.f;

    // prologue: stage k0 = 0
    float4 xa = rok ? *(const float4*)(Xp) : make_float4(0.f,0.f,0.f,0.f);
    float4 wb = *(const float4*)(W + (size_t)bk * 128 + bn);
    As[0][lk4 + 0][lrow] = xa.x;
    As[0][lk4 + 1][lrow] = xa.y;
    As[0][lk4 + 2][lrow] = xa.z;
    As[0][lk4 + 3][lrow] = xa.w;
    *(float4*)&Bs[0][bk][bn] = wb;
    __syncthreads();

    int buf = 0;
#pragma unroll
    for (int k0 = 0; k0 < 128; k0 += 8) {
        float4 xn, wn;
        bool has_next = (k0 + 8 < 128);
        if (has_next) {
            xn = rok ? *(const float4*)(Xp + k0 + 8)
                     : make_float4(0.f,0.f,0.f,0.f);
            wn = *(const float4*)(W + (size_t)(k0 + 8 + bk) * 128 + bn);
        }

#pragma unroll
        for (int kk = 0; kk < 8; kk++) {
            float a[8], b[8];
            float4 a0 = *(const float4*)&As[buf][kk][ty * 8];
            float4 a1 = *(const float4*)&As[buf][kk][ty * 8 + 4];
            a[0]=a0.x; a[1]=a0.y; a[2]=a0.z; a[3]=a0.w;
            a[4]=a1.x; a[5]=a1.y; a[6]=a1.z; a[7]=a1.w;
            float4 b0 = *(const float4*)&Bs[buf][kk][tx * 8];
            float4 b1 = *(const float4*)&Bs[buf][kk][tx * 8 + 4];
            b[0]=b0.x; b[1]=b0.y; b[2]=b0.z; b[3]=b0.w;
            b[4]=b1.x; b[5]=b1.y; b[6]=b1.z; b[7]=b1.w;
#pragma unroll
            for (int i = 0; i < 8; i++)
#pragma unroll
                for (int j = 0; j < 8; j++)
                    acc[i][j] += a[i] * b[j];
        }

        if (has_next) {
            int nb = buf ^ 1;
            As[nb][lk4 + 0][lrow] = xn.x;
            As[nb][lk4 + 1][lrow] = xn.y;
            As[nb][lk4 + 2][lrow] = xn.z;
            As[nb][lk4 + 3][lrow] = xn.w;
            *(float4*)&Bs[nb][bk][bn] = wn;
            __syncthreads();
            buf = nb;
        }
    }

#pragma unroll
    for (int i = 0; i < 8; i++) {
        int orow = row0 + ty * 8 + i;
        if (orow < nrows) {
            float4 v0 = make_float4(acc[i][0], acc[i][1], acc[i][2], acc[i][3]);
            float4 v1 = make_float4(acc[i][4], acc[i][5], acc[i][6], acc[i][7]);
            *(float4*)(Y + (size_t)orow * 128 + tx * 8)     = v0;
            *(float4*)(Y + (size_t)orow * 128 + tx * 8 + 4) = v1;
        }
    }
}

// ---------------- CSR build (both relations per launch) ------------------------
__global__ void hist2_kernel(const int* __restrict__ e_w, int Ew,
                             const int* __restrict__ e_c, int Ec) {
    int rel = blockIdx.y;
    const int* e = rel ? e_c : e_w;
    int E = rel ? Ec : Ew;
    int i = blockIdx.x * blockDim.x + threadIdx.x;
    if (i < E) atomicAdd(&g_deg[rel][e[E + i]], 1);
}

__global__ void scan_kernel(int n) {
    int rel = blockIdx.x;
    __shared__ int sm[1024];
    __shared__ int carry;
    int tid = threadIdx.x;
    if (tid == 0) carry = 0;
    __syncthreads();
    for (int base = 0; base < n; base += 1024) {
        int i = base + tid;
        int v = (i < n) ? g_deg[rel][i] : 0;
        sm[tid] = v;
        __syncthreads();
#pragma unroll
        for (int ofs = 1; ofs < 1024; ofs <<= 1) {
            int t = (tid >= ofs) ? sm[tid - ofs] : 0;
            __syncthreads();
            sm[tid] += t;
            __syncthreads();
        }
        if (i < n) g_off[rel][i] = carry + sm[tid] - v;
        int tot = sm[1023];
        __syncthreads();
        if (tid == 0) carry += tot;
        __syncthreads();
    }
    if (tid == 0) g_off[rel][n] = carry;
}

__global__ void scatter2_kernel(const int* __restrict__ e_w, int Ew,
                                const int* __restrict__ e_c, int Ec) {
    int rel = blockIdx.y;
    const int* e = rel ? e_c : e_w;
    int E = rel ? Ec : Ew;
    int i = blockIdx.x * blockDim.x + threadIdx.x;
    if (i < E) {
        int src = e[i];
        int dst = e[E + i];
        int p = atomicAdd(&g_cur[rel][dst], 1);
        g_csr[rel][g_off[rel][dst] + p] = src;
    }
}

// ---------------- per-destination online-softmax, both relations ---------------
// one warp per destination; lane l holds feature elements [4l, 4l+4);
// heads are 8-lane groups (D=32 = 8 lanes x 4 elems).
__device__ __forceinline__ void rel_agg(
    const float* __restrict__ rk, const float* __restrict__ rv,
    const int* __restrict__ csr, int beg, int end,
    float4 q4, int lane, float4& acc, float& s) {
    float m = -INFINITY;
    s = 0.f;
    acc = make_float4(0.f, 0.f, 0.f, 0.f);
    const float scale = 0.17677669529663687f;   // 1/sqrt(32)

    int e = beg;
    for (; e + 2 <= end; e += 2) {
        int s0 = csr[e], s1 = csr[e + 1];
        const float4 k0 = *(const float4*)(rk + (size_t)s0 * 128 + lane * 4);
        const float4 k1 = *(const float4*)(rk + (size_t)s1 * 128 + lane * 4);
        float p0 = q4.x*k0.x + q4.y*k0.y + q4.z*k0.z + q4.w*k0.w;
        float p1 = q4.x*k1.x + q4.y*k1.y + q4.z*k1.z + q4.w*k1.w;
        p0 += __shfl_xor_sync(0xFFFFFFFFu, p0, 1);
        p1 += __shfl_xor_sync(0xFFFFFFFFu, p1, 1);
        p0 += __shfl_xor_sync(0xFFFFFFFFu, p0, 2);
        p1 += __shfl_xor_sync(0xFFFFFFFFu, p1, 2);
        p0 += __shfl_xor_sync(0xFFFFFFFFu, p0, 4);
        p1 += __shfl_xor_sync(0xFFFFFFFFu, p1, 4);
        const float4 v0 = *(const float4*)(rv + (size_t)s0 * 128 + lane * 4);
        const float4 v1 = *(const float4*)(rv + (size_t)s1 * 128 + lane * 4);
        float sc0 = p0 * scale, sc1 = p1 * scale;
        float nm = fmaxf(m, fmaxf(sc0, sc1));
        float corr = __expf(m - nm);
        float pe0 = __expf(sc0 - nm);
        float pe1 = __expf(sc1 - nm);
        s = s * corr + pe0 + pe1;
        acc.x = acc.x * corr + pe0 * v0.x + pe1 * v1.x;
        acc.y = acc.y * corr + pe0 * v0.y + pe1 * v1.y;
        acc.z = acc.z * corr + pe0 * v0.z + pe1 * v1.z;
        acc.w = acc.w * corr + pe0 * v0.w + pe1 * v1.w;
        m = nm;
    }
    if (e < end) {
        int s0 = csr[e];
        const float4 k0 = *(const float4*)(rk + (size_t)s0 * 128 + lane * 4);
        float p0 = q4.x*k0.x + q4.y*k0.y + q4.z*k0.z + q4.w*k0.w;
        p0 += __shfl_xor_sync(0xFFFFFFFFu, p0, 1);
        p0 += __shfl_xor_sync(0xFFFFFFFFu, p0, 2);
        p0 += __shfl_xor_sync(0xFFFFFFFFu, p0, 4);
        const float4 v0 = *(const float4*)(rv + (size_t)s0 * 128 + lane * 4);
        float sc0 = p0 * scale;
        float nm = fmaxf(m, sc0);
        float corr = __expf(m - nm);
        float pe0 = __expf(sc0 - nm);
        s = s * corr + pe0;
        acc.x = acc.x * corr + pe0 * v0.x;
        acc.y = acc.y * corr + pe0 * v0.y;
        acc.z = acc.z * corr + pe0 * v0.z;
        acc.w = acc.w * corr + pe0 * v0.w;
    }
}

__global__ __launch_bounds__(256) void aggregate2_kernel(int n) {
    int warp = (blockIdx.x * blockDim.x + threadIdx.x) >> 5;
    if (warp >= n) return;
    int lane = threadIdx.x & 31;

    float4 q4 = *(const float4*)(g_qp + (size_t)warp * 128 + lane * 4);

    float4 aw, ac;
    float sw, sc;
    int bw = g_off[0][warp], ew = g_off[0][warp + 1];
    int bc = g_off[1][warp], ec = g_off[1][warp + 1];
    rel_agg(g_rkw, g_rvw, g_csr[0], bw, ew, q4, lane, aw, sw);
    rel_agg(g_rkc, g_rvc, g_csr[1], bc, ec, q4, lane, ac, sc);

    float iw = (ew > bw) ? 1.f / sw : 0.f;
    float ic = (ec > bc) ? 1.f / sc : 0.f;
    float4 o;
    o.x = aw.x * iw + ac.x * ic;
    o.y = aw.y * iw + ac.y * ic;
    o.z = aw.z * iw + ac.z * ic;
    o.w = aw.w * iw + ac.w * ic;
    *(float4*)(g_outp + (size_t)warp * 128 + lane * 4) = o;
}

// ---------------- final projections (both node types, one launch) --------------
__global__ __launch_bounds__(256) void final_kernel(
    const float* __restrict__ Xa, const float* __restrict__ Xp,
    const float* __restrict__ Wr_a, const float* __restrict__ Wo_p,
    const float* __restrict__ Wr_p, const float* __restrict__ bo_a,
    const float* __restrict__ bo_p, float* __restrict__ out, int n) {
    int type = blockIdx.y;     // 0 = author, 1 = paper
    __shared__ float Ws[2 * 128 * 32];
    if (type == 0) {
        for (int i = threadIdx.x; i < 4096; i += blockDim.x) Ws[i] = Wr_a[i];
    } else {
        for (int i = threadIdx.x; i < 4096; i += blockDim.x) Ws[i] = Wo_p[i];
        for (int i = threadIdx.x; i < 4096; i += blockDim.x) Ws[4096 + i] = Wr_p[i];
    }
    __syncthreads();
    int warp = blockIdx.x * (blockDim.x >> 5) + (threadIdx.x >> 5);
    int lane = threadIdx.x & 31;
    if (warp >= n) return;

    if (type == 0) {
        const float* xr = Xa + (size_t)warp * 128;
        float acc = bo_a[lane];
#pragma unroll 8
        for (int k = 0; k < 128; k++) acc += xr[k] * Ws[k * 32 + lane];
        out[(size_t)warp * 32 + lane] = acc;
    } else {
        const float* op = g_outp + (size_t)warp * 128;
        const float* xr = Xp + (size_t)warp * 128;
        float acc = bo_p[lane];
#pragma unroll 8
        for (int k = 0; k < 128; k++) acc += op[k] * Ws[k * 32 + lane];
#pragma unroll 8
        for (int k = 0; k < 128; k++) acc += xr[k] * Ws[4096 + k * 32 + lane];
        out[(size_t)(n + warp) * 32 + lane] = acc;
    }
}

// ---------------- launch --------------------------------------------------------
extern "C" void kernel_launch(void* const* d_in, const int* in_sizes, int n_in,
                              void* d_out, int out_size) {
    const float* x_a   = (const float*)d_in[0];
    const float* x_p   = (const float*)d_in[1];
    const int*   e_w   = (const int*)d_in[2];
    const int*   e_c   = (const int*)d_in[3];
    const float* wk_a  = (const float*)d_in[5];
    const float* wv_a  = (const float*)d_in[6];
    const float* wq_p  = (const float*)d_in[7];
    const float* wk_p  = (const float*)d_in[8];
    const float* wv_p  = (const float*)d_in[9];
    const float* wrk_w = (const float*)d_in[10];
    const float* wrv_w = (const float*)d_in[11];
    const float* wrk_c = (const float*)d_in[12];
    const float* wrv_c = (const float*)d_in[13];
    const float* bo_a  = (const float*)d_in[15];
    const float* wo_p  = (const float*)d_in[16];
    const float* bo_p  = (const float*)d_in[17];
    const float* wr_a  = (const float*)d_in[18];
    const float* wr_p  = (const float*)d_in[19];
    float* out = (float*)d_out;

    int n  = in_sizes[0] / 128;
    int Ew = in_sizes[2] / 2;
    int Ec = in_sizes[3] / 2;

    init_zero<<<(n + 255) / 256, 256>>>(n);
    compose_kernel<<<dim3(128, 4), 128>>>(wk_a, wrk_w, wv_a, wrv_w,
                                          wk_p, wrk_c, wv_p, wrv_c);

    int gb = (n + 127) / 128;
    sgemm_fused<<<dim3(gb, 5), 256>>>(x_a, x_p, wq_p, n);

    int geb = (((Ew > Ec) ? Ew : Ec) + 255) / 256;
    hist2_kernel<<<dim3(geb, 2), 256>>>(e_w, Ew, e_c, Ec);
    scan_kernel<<<2, 1024>>>(n);
    scatter2_kernel<<<dim3(geb, 2), 256>>>(e_w, Ew, e_c, Ec);

    int ga = (n + 7) / 8;   // 8 warps per 256-thread block
    aggregate2_kernel<<<ga, 256>>>(n);

    int gf = (n + 7) / 8;
    final_kernel<<<dim3(gf, 2), 256>>>(x_a, x_p, wr_a, wo_p, wr_p,
                                       bo_a, bo_p, out, n);
}